// round 9
// baseline (speedup 1.0000x reference)
#include <cuda_runtime.h>
#include <stdint.h>

#define BB 4
#define QQ 256
#define MMM 256
#define HH 512
#define DQS 512
#define DKS 512
#define DC (DQS + DKS)

// Scratch device globals
__device__ float g_qproj[BB * QQ * HH];    // 2 MB
__device__ float g_kproj[BB * MMM * HH];   // 2 MB
__device__ float g_logits[BB * QQ * MMM];  // 1 MB (masked logits)
__device__ float g_partial[BB * QQ * DQS]; // 2 MB  query @ Wo1^T + bo
__device__ float g_P2[BB * MMM * DQS];     // 2 MB  memory @ Wo2^T

// ---------------------------------------------------------------------------
// helpers
// ---------------------------------------------------------------------------
__device__ __forceinline__ float f2tf32(float x) {
    uint32_t r;
    asm("cvt.rna.tf32.f32 %0, %1;" : "=r"(r) : "f"(x));
    return __uint_as_float(r);
}
__device__ __forceinline__ uint32_t fu(float x) { return __float_as_uint(x); }

__device__ __forceinline__ uint32_t pack_f16x2(float hi, float lo) {
    uint32_t r;
    asm("cvt.rn.f16x2.f32 %0, %1, %2;" : "=r"(r) : "f"(hi), "f"(lo));
    return r;
}

__device__ __forceinline__ void mma_tf32(float c[4], const uint32_t a[4],
                                         const uint32_t b[2]) {
    asm volatile(
        "mma.sync.aligned.m16n8k8.row.col.f32.tf32.tf32.f32 "
        "{%0,%1,%2,%3}, {%4,%5,%6,%7}, {%8,%9}, {%0,%1,%2,%3};"
        : "+f"(c[0]), "+f"(c[1]), "+f"(c[2]), "+f"(c[3])
        : "r"(a[0]), "r"(a[1]), "r"(a[2]), "r"(a[3]), "r"(b[0]), "r"(b[1]));
}

__device__ __forceinline__ uint32_t smem_u32(const void* p) {
    return (uint32_t)__cvta_generic_to_shared(p);
}
__device__ __forceinline__ void cp_async16(uint32_t dst, const void* src) {
    asm volatile("cp.async.cg.shared.global [%0], [%1], 16;" :: "r"(dst), "l"(src));
}
__device__ __forceinline__ void cp_commit() {
    asm volatile("cp.async.commit_group;");
}
template<int N> __device__ __forceinline__ void cp_wait() {
    asm volatile("cp.async.wait_group %0;" :: "n"(N));
}

// ---------------------------------------------------------------------------
// K1: qproj + kproj (NT), cp.async 2-stage, 64x64 tile, BK=32, 256 thr.
// raw f32 in smem; cvt.rna.tf32 after LDS (numerics identical to explicit cvt).
// ---------------------------------------------------------------------------
__device__ __forceinline__ void gemm_nt_cp(
    float (*As)[64][36], float (*Ws)[64][36],
    int row0, int col0,
    const float* __restrict__ A, int lda,
    const float* __restrict__ W, int ldw,
    const float* __restrict__ bias,
    float* __restrict__ C, int ldc, int K)
{
    const int tid  = threadIdx.x;
    const int lane = tid & 31;
    const int g    = lane >> 2;
    const int tg   = lane & 3;
    const int w    = tid >> 5;
    const int wm   = (w >> 2) << 5;
    const int wn   = (w & 3) << 4;

    int lr[2], lc[2];
#pragma unroll
    for (int c = 0; c < 2; c++) {
        int idx = tid + (c << 8);
        lr[c] = idx >> 3;
        lc[c] = (idx & 7) << 2;
    }

    const int nk = K >> 5;

    // prologue: stage 0
#pragma unroll
    for (int c = 0; c < 2; c++) {
        cp_async16(smem_u32(&As[0][lr[c]][lc[c]]),
                   A + (size_t)(row0 + lr[c]) * lda + lc[c]);
        cp_async16(smem_u32(&Ws[0][lr[c]][lc[c]]),
                   W + (size_t)(col0 + lr[c]) * ldw + lc[c]);
    }
    cp_commit();

    float acc[2][2][4];
#pragma unroll
    for (int mi = 0; mi < 2; mi++)
#pragma unroll
        for (int ni = 0; ni < 2; ni++)
#pragma unroll
            for (int j = 0; j < 4; j++) acc[mi][ni][j] = 0.f;

    for (int i = 0; i < nk; i++) {
        cp_wait<0>();
        __syncthreads();     // stage i ready; everyone done computing i-1
        if (i + 1 < nk) {
            int kn = (i + 1) << 5;
            int nb = (i + 1) & 1;
#pragma unroll
            for (int c = 0; c < 2; c++) {
                cp_async16(smem_u32(&As[nb][lr[c]][lc[c]]),
                           A + (size_t)(row0 + lr[c]) * lda + kn + lc[c]);
                cp_async16(smem_u32(&Ws[nb][lr[c]][lc[c]]),
                           W + (size_t)(col0 + lr[c]) * ldw + kn + lc[c]);
            }
            cp_commit();
        }
        const int buf = i & 1;
#pragma unroll
        for (int ks = 0; ks < 4; ks++) {
            const int kk = ks << 3;
            uint32_t af[2][4], bf[2][2];
#pragma unroll
            for (int mi = 0; mi < 2; mi++) {
                int r = wm + (mi << 4) + g;
                af[mi][0] = fu(f2tf32(As[buf][r][kk + tg]));
                af[mi][1] = fu(f2tf32(As[buf][r + 8][kk + tg]));
                af[mi][2] = fu(f2tf32(As[buf][r][kk + tg + 4]));
                af[mi][3] = fu(f2tf32(As[buf][r + 8][kk + tg + 4]));
            }
#pragma unroll
            for (int ni = 0; ni < 2; ni++) {
                int cn = wn + (ni << 3) + g;
                bf[ni][0] = fu(f2tf32(Ws[buf][cn][kk + tg]));
                bf[ni][1] = fu(f2tf32(Ws[buf][cn][kk + tg + 4]));
            }
#pragma unroll
            for (int mi = 0; mi < 2; mi++)
#pragma unroll
                for (int ni = 0; ni < 2; ni++)
                    mma_tf32(acc[mi][ni], af[mi], bf[ni]);
        }
    }

#pragma unroll
    for (int mi = 0; mi < 2; mi++) {
#pragma unroll
        for (int ni = 0; ni < 2; ni++) {
            int col = col0 + wn + (ni << 3) + (tg << 1);
            float b0 = bias ? bias[col] : 0.f;
            float b1 = bias ? bias[col + 1] : 0.f;
            int r0 = row0 + wm + (mi << 4) + g;
            int r1 = r0 + 8;
            *reinterpret_cast<float2*>(C + (size_t)r0 * ldc + col) =
                make_float2(acc[mi][ni][0] + b0, acc[mi][ni][1] + b1);
            *reinterpret_cast<float2*>(C + (size_t)r1 * ldc + col) =
                make_float2(acc[mi][ni][2] + b0, acc[mi][ni][3] + b1);
        }
    }
}

__global__ void __launch_bounds__(256) k1_proj(
    const float* __restrict__ query, const float* __restrict__ memory,
    const float* __restrict__ Wq, const float* __restrict__ bq,
    const float* __restrict__ Wk, const float* __restrict__ bk)
{
    __shared__ float As[2][64][36];
    __shared__ float Ws[2][64][36];
    const int t = blockIdx.x & 127;
    const int row0 = (t >> 3) << 6;
    const int col0 = (t & 7) << 6;
    if (blockIdx.x < 128)
        gemm_nt_cp(As, Ws, row0, col0, query, DQS, Wq, DQS, bq, g_qproj, HH, DQS);
    else
        gemm_nt_cp(As, Ws, row0, col0, memory, DKS, Wk, DKS, bk, g_kproj, HH, DKS);
}

// ---------------------------------------------------------------------------
// NT GEMM body for k2's fused blocks (register-prefetch double buffer,
// unchanged from round 7 — hidden under scores).
// ---------------------------------------------------------------------------
template<bool BIAS>
__device__ __forceinline__ void gemm_nt_256(
    float (*Asb)[64][36], float (*Wsb)[64][36],
    int row0, int col0,
    const float* __restrict__ A, int lda,
    const float* __restrict__ W, int ldw,
    const float* __restrict__ bias,
    float* __restrict__ C, int ldc, int K)
{
    const int tid  = threadIdx.x;
    const int lane = tid & 31;
    const int g    = lane >> 2;
    const int tg   = lane & 3;
    const int w    = tid >> 5;
    const int wm   = (w >> 2) << 5;
    const int wn   = (w & 3) << 4;

    int lr[2], lc[2];
#pragma unroll
    for (int c = 0; c < 2; c++) {
        int idx = tid + (c << 8);
        lr[c] = idx >> 3;
        lc[c] = (idx & 7) << 2;
    }

    float acc[2][2][4];
#pragma unroll
    for (int mi = 0; mi < 2; mi++)
#pragma unroll
        for (int ni = 0; ni < 2; ni++)
#pragma unroll
            for (int j = 0; j < 4; j++) acc[mi][ni][j] = 0.f;

    float4 pa[2], pw[2];
#pragma unroll
    for (int c = 0; c < 2; c++) {
        pa[c] = *reinterpret_cast<const float4*>(A + (size_t)(row0 + lr[c]) * lda + lc[c]);
        pw[c] = *reinterpret_cast<const float4*>(W + (size_t)(col0 + lr[c]) * ldw + lc[c]);
    }

    int buf = 0;
    for (int k0 = 0; k0 < K; k0 += 32) {
#pragma unroll
        for (int c = 0; c < 2; c++) {
            float4 va = pa[c], vw = pw[c];
            *reinterpret_cast<float4*>(&Asb[buf][lr[c]][lc[c]]) =
                make_float4(f2tf32(va.x), f2tf32(va.y), f2tf32(va.z), f2tf32(va.w));
            *reinterpret_cast<float4*>(&Wsb[buf][lr[c]][lc[c]]) =
                make_float4(f2tf32(vw.x), f2tf32(vw.y), f2tf32(vw.z), f2tf32(vw.w));
        }
        __syncthreads();

        int kn = k0 + 32;
        if (kn < K) {
#pragma unroll
            for (int c = 0; c < 2; c++) {
                pa[c] = *reinterpret_cast<const float4*>(
                    A + (size_t)(row0 + lr[c]) * lda + kn + lc[c]);
                pw[c] = *reinterpret_cast<const float4*>(
                    W + (size_t)(col0 + lr[c]) * ldw + kn + lc[c]);
            }
        }

#pragma unroll
        for (int ks = 0; ks < 4; ks++) {
            const int kk = ks << 3;
            uint32_t af[2][4], bf[2][2];
#pragma unroll
            for (int mi = 0; mi < 2; mi++) {
                int r = wm + (mi << 4) + g;
                af[mi][0] = fu(Asb[buf][r][kk + tg]);
                af[mi][1] = fu(Asb[buf][r + 8][kk + tg]);
                af[mi][2] = fu(Asb[buf][r][kk + tg + 4]);
                af[mi][3] = fu(Asb[buf][r + 8][kk + tg + 4]);
            }
#pragma unroll
            for (int ni = 0; ni < 2; ni++) {
                int cn = wn + (ni << 3) + g;
                bf[ni][0] = fu(Wsb[buf][cn][kk + tg]);
                bf[ni][1] = fu(Wsb[buf][cn][kk + tg + 4]);
            }
#pragma unroll
            for (int mi = 0; mi < 2; mi++)
#pragma unroll
                for (int ni = 0; ni < 2; ni++)
                    mma_tf32(acc[mi][ni], af[mi], bf[ni]);
        }
        buf ^= 1;
    }

#pragma unroll
    for (int mi = 0; mi < 2; mi++) {
#pragma unroll
        for (int ni = 0; ni < 2; ni++) {
            int col = col0 + wn + (ni << 3) + (tg << 1);
            float b0 = 0.f, b1 = 0.f;
            if (BIAS) { b0 = bias[col]; b1 = bias[col + 1]; }
            int r0 = row0 + wm + (mi << 4) + g;
            int r1 = r0 + 8;
            *reinterpret_cast<float2*>(C + (size_t)r0 * ldc + col) =
                make_float2(acc[mi][ni][0] + b0, acc[mi][ni][1] + b1);
            *reinterpret_cast<float2*>(C + (size_t)r1 * ldc + col) =
                make_float2(acc[mi][ni][2] + b0, acc[mi][ni][3] + b1);
        }
    }
}

// ---------------------------------------------------------------------------
// Scores body (f16x2 tanh). Writes MASKED logits (-1e18 on masked m).
// ---------------------------------------------------------------------------
__device__ __forceinline__ void scores_body(int bid, float (*ks)[512],
                                            const float* __restrict__ Wl,
                                            const unsigned int* __restrict__ mask)
{
    const int b  = bid >> 7;
    const int qg = (bid >> 2) & 31;
    const int mg = bid & 3;
    const int q0 = qg << 3;
    const int m0base = mg << 6;

    const int tid = threadIdx.x;
    const int lane = tid & 31;
    const int w = tid >> 5;
    const int q = q0 + w;

    float qr[16];
    uint32_t wlp[8];
    const float* qp = g_qproj + ((size_t)(b * QQ + q)) * HH;
#pragma unroll
    for (int j = 0; j < 16; j++) qr[j] = qp[lane + 32 * j];
#pragma unroll
    for (int jp = 0; jp < 8; jp++)
        wlp[jp] = pack_f16x2(Wl[lane + 64 * jp + 32], Wl[lane + 64 * jp]);

    float* lout = g_logits + ((size_t)(b * QQ + q)) * MMM;
    const unsigned int* mrow = mask + b * MMM;

    for (int t = 0; t < 4; t++) {
        const int m0 = m0base + (t << 4);
        __syncthreads();
        const float* kp = g_kproj + ((size_t)(b * MMM + m0)) * HH;
#pragma unroll
        for (int i = 0; i < 8; i++) {
            int idx = tid + (i << 8);
            int mm = idx >> 7;
            int c4 = (idx & 127) << 2;
            *reinterpret_cast<float4*>(&ks[mm][c4]) =
                *reinterpret_cast<const float4*>(kp + mm * HH + c4);
        }
        __syncthreads();

#pragma unroll 4
        for (int mm = 0; mm < 16; mm++) {
            uint32_t acch = 0;
#pragma unroll
            for (int jp = 0; jp < 8; jp++) {
                float s0 = qr[2 * jp]     + ks[mm][lane + 64 * jp];
                float s1 = qr[2 * jp + 1] + ks[mm][lane + 64 * jp + 32];
                uint32_t sp = pack_f16x2(s1, s0);
                uint32_t tp;
                asm("tanh.approx.f16x2 %0, %1;" : "=r"(tp) : "r"(sp));
                asm("fma.rn.f16x2 %0, %1, %2, %0;" : "+r"(acch)
                    : "r"(tp), "r"(wlp[jp]));
            }
            float flo, fhi;
            asm("{ .reg .b16 l, h;\n"
                "  mov.b32 {l, h}, %2;\n"
                "  cvt.f32.f16 %0, l;\n"
                "  cvt.f32.f16 %1, h; }"
                : "=f"(flo), "=f"(fhi) : "r"(acch));
            float acc = flo + fhi;
#pragma unroll
            for (int o = 16; o > 0; o >>= 1)
                acc += __shfl_xor_sync(0xFFFFFFFFu, acc, o);
            if (lane == 0)
                lout[m0 + mm] = (mrow[m0 + mm] != 0u) ? -1e18f : acc;
        }
    }
}

// ---------------------------------------------------------------------------
// K2: scores (512) + partial=query@Wo1^T+bo (128) + P2=memory@Wo2^T (128).
// ---------------------------------------------------------------------------
__global__ void __launch_bounds__(256) k2_scores_fused(
    const float* __restrict__ query, const float* __restrict__ memory,
    const float* __restrict__ Wo, const float* __restrict__ bo,
    const float* __restrict__ Wl, const unsigned int* __restrict__ mask)
{
    __shared__ __align__(16) union {
        float ks[16][512];
        struct { float As[2][64][36]; float Ws[2][64][36]; } g;
    } sm;

    const int bid = blockIdx.x;
    if (bid < 512) {
        scores_body(bid, sm.ks, Wl, mask);
    } else if (bid < 640) {
        const int t = bid - 512;
        gemm_nt_256<true>(sm.g.As, sm.g.Ws, (t >> 3) << 6, (t & 7) << 6,
                          query, DQS, Wo, DC, bo, g_partial, DQS, DQS);
    } else {
        const int t = bid - 640;
        gemm_nt_256<false>(sm.g.As, sm.g.Ws, (t >> 3) << 6, (t & 7) << 6,
                           memory, DKS, Wo + DQS, DC, nullptr, g_P2, DQS, DKS);
    }
}

// ---------------------------------------------------------------------------
// K4: fused softmax + final GEMM.
//   prologue: per-row (max, 1/sum) from masked logits; col0==0 blocks also
//             write the weights output.
//   mainloop: A = softmax(logits) materialized on the fly from cp.async'd raw
//             logit tiles; B = P2 via cp.async. 2-stage each.
//   out = tanh(partial + softmax(logits) @ P2)
// ---------------------------------------------------------------------------
__global__ void __launch_bounds__(256) k4_final(
    float* __restrict__ out, float* __restrict__ weights)
{
    const int bid = blockIdx.x;
    const int b = bid >> 5;
    const int tile = bid & 31;
    const int row0 = (tile >> 3) << 6;   // q-tile
    const int col0 = (tile & 7) << 6;    // o-tile

    const float* L  = g_logits + ((size_t)(b * QQ) + row0) * MMM;  // 64 x 256
    const float* Bm = g_P2 + (size_t)b * MMM * DQS;

    __shared__ float Ls[2][64][36];
    __shared__ float Bs[2][32][72];
    __shared__ float row_c[64];    // -max * log2e
    __shared__ float row_inv[64];  // 1 / sum

    const int tid  = threadIdx.x;
    const int lane = tid & 31;
    const int g    = lane >> 2;
    const int tg   = lane & 3;
    const int w    = tid >> 5;
    const int wm   = (w >> 2) << 5;
    const int wn   = (w & 3) << 4;

    const float LOG2E = 1.4426950408889634f;

    // ---- softmax stats: warp w handles rows w*8 .. w*8+7 ----
    for (int rr = 0; rr < 8; rr++) {
        int r = (w << 3) + rr;
        const float* lp = L + (size_t)r * MMM;
        float v[8];
        float mx = -3.4e38f;
#pragma unroll
        for (int j = 0; j < 8; j++) {
            v[j] = lp[lane + 32 * j];
            mx = fmaxf(mx, v[j]);
        }
#pragma unroll
        for (int o = 16; o > 0; o >>= 1)
            mx = fmaxf(mx, __shfl_xor_sync(0xFFFFFFFFu, mx, o));
        float s = 0.f;
#pragma unroll
        for (int j = 0; j < 8; j++) s += __expf(v[j] - mx);
#pragma unroll
        for (int o = 16; o > 0; o >>= 1)
            s += __shfl_xor_sync(0xFFFFFFFFu, s, o);
        if (lane == 0) {
            row_c[r]   = -mx * LOG2E;
            row_inv[r] = 1.f / s;
        }
    }
    __syncthreads();

    // ---- weights output (blocks with col0 == 0 cover all [b, q]) ----
    if (col0 == 0) {
        for (int rr = 0; rr < 8; rr++) {
            int r = (w << 3) + rr;
            const float* lp = L + (size_t)r * MMM;
            float c = row_c[r], inv = row_inv[r];
            float* wo = weights + ((size_t)(b * QQ) + row0 + r) * MMM;
#pragma unroll
            for (int j = 0; j < 8; j++) {
                float x = lp[lane + 32 * j];
                wo[lane + 32 * j] = exp2f(fmaf(x, LOG2E, c)) * inv;
            }
        }
    }

    // ---- pipelined mainloop (K = 256, 8 iters) ----
    int la_r[2], la_c[2], lb_r[2], lb_c[2];
#pragma unroll
    for (int c = 0; c < 2; c++) {
        int idx = tid + (c << 8);
        la_r[c] = idx >> 3;  la_c[c] = (idx & 7) << 2;    // 64 x 8 f4
        lb_r[c] = idx >> 4;  lb_c[c] = (idx & 15) << 2;   // 32 x 16 f4
    }

#pragma unroll
    for (int c = 0; c < 2; c++) {
        cp_async16(smem_u32(&Ls[0][la_r[c]][la_c[c]]),
                   L + (size_t)la_r[c] * MMM + la_c[c]);
        cp_async16(smem_u32(&Bs[0][lb_r[c]][lb_c[c]]),
                   Bm + (size_t)lb_r[c] * DQS + col0 + lb_c[c]);
    }
    cp_commit();

    float acc[2][2][4];
#pragma unroll
    for (int mi = 0; mi < 2; mi++)
#pragma unroll
        for (int ni = 0; ni < 2; ni++)
#pragma unroll
            for (int j = 0; j < 4; j++) acc[mi][ni][j] = 0.f;

    // per-warp row constants (rows fixed across K)
    float c1[2], i1[2], c2[2], i2[2];
#pragma unroll
    for (int mi = 0; mi < 2; mi++) {
        int r = wm + (mi << 4) + g;
        c1[mi] = row_c[r];     i1[mi] = row_inv[r];
        c2[mi] = row_c[r + 8]; i2[mi] = row_inv[r + 8];
    }

    for (int i = 0; i < 8; i++) {
        cp_wait<0>();
        __syncthreads();
        if (i + 1 < 8) {
            int kn = (i + 1) << 5;
            int nb = (i + 1) & 1;
#pragma unroll
            for (int c = 0; c < 2; c++) {
                cp_async16(smem_u32(&Ls[nb][la_r[c]][la_c[c]]),
                           L + (size_t)la_r[c] * MMM + kn + la_c[c]);
                cp_async16(smem_u32(&Bs[nb][lb_r[c]][lb_c[c]]),
                           Bm + (size_t)(kn + lb_r[c]) * DQS + col0 + lb_c[c]);
            }
            cp_commit();
        }
        const int buf = i & 1;
#pragma unroll
        for (int ks = 0; ks < 4; ks++) {
            const int kk = ks << 3;
            uint32_t af[2][4], bf[2][2];
#pragma unroll
            for (int mi = 0; mi < 2; mi++) {
                int r = wm + (mi << 4) + g;
                af[mi][0] = fu(f2tf32(exp2f(fmaf(Ls[buf][r][kk + tg],     LOG2E, c1[mi])) * i1[mi]));
                af[mi][1] = fu(f2tf32(exp2f(fmaf(Ls[buf][r + 8][kk + tg], LOG2E, c2[mi])) * i2[mi]));
                af[mi][2] = fu(f2tf32(exp2f(fmaf(Ls[buf][r][kk + tg + 4],     LOG2E, c1[mi])) * i1[mi]));
                af[mi][3] = fu(f2tf32(exp2f(fmaf(Ls[buf][r + 8][kk + tg + 4], LOG2E, c2[mi])) * i2[mi]));
            }
#pragma unroll
            for (int ni = 0; ni < 2; ni++) {
                int cn = wn + (ni << 3) + g;
                bf[ni][0] = fu(f2tf32(Bs[buf][kk + tg][cn]));
                bf[ni][1] = fu(f2tf32(Bs[buf][kk + tg + 4][cn]));
            }
#pragma unroll
            for (int mi = 0; mi < 2; mi++)
#pragma unroll
                for (int ni = 0; ni < 2; ni++)
                    mma_tf32(acc[mi][ni], af[mi], bf[ni]);
        }
    }

    // ---- epilogue: tanh(acc + partial) ----
#pragma unroll
    for (int mi = 0; mi < 2; mi++) {
#pragma unroll
        for (int ni = 0; ni < 2; ni++) {
            int col = col0 + wn + (ni << 3) + (tg << 1);
            size_t r0 = (size_t)b * QQ + row0 + wm + (mi << 4) + g;
            size_t r1 = r0 + 8;
            float2 p0 = *reinterpret_cast<const float2*>(&g_partial[r0 * DQS + col]);
            float2 p1 = *reinterpret_cast<const float2*>(&g_partial[r1 * DQS + col]);
            *reinterpret_cast<float2*>(out + r0 * DQS + col) =
                make_float2(tanhf(acc[mi][ni][0] + p0.x), tanhf(acc[mi][ni][1] + p0.y));
            *reinterpret_cast<float2*>(out + r1 * DQS + col) =
                make_float2(tanhf(acc[mi][ni][2] + p1.x), tanhf(acc[mi][ni][3] + p1.y));
        }
    }
}

// ---------------------------------------------------------------------------
// Launch
// ---------------------------------------------------------------------------
extern "C" void kernel_launch(void* const* d_in, const int* in_sizes, int n_in,
                              void* d_out, int out_size)
{
    const float* query  = (const float*)d_in[0];
    const float* memory = (const float*)d_in[1];
    const unsigned int* mask = (const unsigned int*)d_in[2];
    const float* Wk = (const float*)d_in[3];
    const float* bk = (const float*)d_in[4];
    const float* Wq = (const float*)d_in[5];
    const float* bq = (const float*)d_in[6];
    const float* Wl = (const float*)d_in[7];
    // d_in[8] = bl (uniform shift — cancels in softmax)
    const float* Wo = (const float*)d_in[9];
    const float* bo = (const float*)d_in[10];

    float* out     = (float*)d_out;
    float* weights = out + BB * QQ * DQS;

    k1_proj<<<256, 256>>>(query, memory, Wq, bq, Wk, bk);
    k2_scores_fused<<<768, 256>>>(query, memory, Wo, bo, Wl, mask);
    k4_final<<<128, 256>>>(out, weights);
}

// round 10
// speedup vs baseline: 1.0682x; 1.0682x over previous
#include <cuda_runtime.h>
#include <stdint.h>

#define BB 4
#define QQ 256
#define MMM 256
#define HH 512
#define DQS 512
#define DKS 512
#define DC (DQS + DKS)

// Scratch device globals
__device__ float g_qproj[BB * QQ * HH];    // 2 MB
__device__ float g_kproj[BB * MMM * HH];   // 2 MB
__device__ float g_logits[BB * QQ * MMM];  // 1 MB (masked logits)
__device__ float g_partial[BB * QQ * DQS]; // 2 MB  query @ Wo1^T + bo
__device__ float g_P2[BB * MMM * DQS];     // 2 MB  memory @ Wo2^T

// ---------------------------------------------------------------------------
// helpers
// ---------------------------------------------------------------------------
__device__ __forceinline__ float f2tf32(float x) {
    uint32_t r;
    asm("cvt.rna.tf32.f32 %0, %1;" : "=r"(r) : "f"(x));
    return __uint_as_float(r);
}
__device__ __forceinline__ uint32_t fu(float x) { return __float_as_uint(x); }

__device__ __forceinline__ void mma_tf32(float c[4], const uint32_t a[4],
                                         const uint32_t b[2]) {
    asm volatile(
        "mma.sync.aligned.m16n8k8.row.col.f32.tf32.tf32.f32 "
        "{%0,%1,%2,%3}, {%4,%5,%6,%7}, {%8,%9}, {%0,%1,%2,%3};"
        : "+f"(c[0]), "+f"(c[1]), "+f"(c[2]), "+f"(c[3])
        : "r"(a[0]), "r"(a[1]), "r"(a[2]), "r"(a[3]), "r"(b[0]), "r"(b[1]));
}

// ---------------------------------------------------------------------------
// NT tf32 GEMM body, 256 threads, 64x64 tile, BK=32, double-buffered smem,
// register prefetch, cvt AT THE STORE (round-6/7 proven structure).
// 8 warps (2x4), warp tile 32x16. Stride 36 -> conflict-free fragment LDS.
// ---------------------------------------------------------------------------
template<bool BIAS>
__device__ __forceinline__ void gemm_nt_256(
    float (*Asb)[64][36], float (*Wsb)[64][36],
    int row0, int col0,
    const float* __restrict__ A, int lda,
    const float* __restrict__ W, int ldw,
    const float* __restrict__ bias,
    float* __restrict__ C, int ldc, int K)
{
    const int tid  = threadIdx.x;
    const int lane = tid & 31;
    const int g    = lane >> 2;
    const int tg   = lane & 3;
    const int w    = tid >> 5;
    const int wm   = (w >> 2) << 5;
    const int wn   = (w & 3) << 4;

    int lr[2], lc[2];
#pragma unroll
    for (int c = 0; c < 2; c++) {
        int idx = tid + (c << 8);
        lr[c] = idx >> 3;
        lc[c] = (idx & 7) << 2;
    }

    float acc[2][2][4];
#pragma unroll
    for (int mi = 0; mi < 2; mi++)
#pragma unroll
        for (int ni = 0; ni < 2; ni++)
#pragma unroll
            for (int j = 0; j < 4; j++) acc[mi][ni][j] = 0.f;

    float4 pa[2], pw[2];
#pragma unroll
    for (int c = 0; c < 2; c++) {
        pa[c] = *reinterpret_cast<const float4*>(A + (size_t)(row0 + lr[c]) * lda + lc[c]);
        pw[c] = *reinterpret_cast<const float4*>(W + (size_t)(col0 + lr[c]) * ldw + lc[c]);
    }

    int buf = 0;
    for (int k0 = 0; k0 < K; k0 += 32) {
#pragma unroll
        for (int c = 0; c < 2; c++) {
            float4 va = pa[c], vw = pw[c];
            *reinterpret_cast<float4*>(&Asb[buf][lr[c]][lc[c]]) =
                make_float4(f2tf32(va.x), f2tf32(va.y), f2tf32(va.z), f2tf32(va.w));
            *reinterpret_cast<float4*>(&Wsb[buf][lr[c]][lc[c]]) =
                make_float4(f2tf32(vw.x), f2tf32(vw.y), f2tf32(vw.z), f2tf32(vw.w));
        }
        __syncthreads();

        int kn = k0 + 32;
        if (kn < K) {
#pragma unroll
            for (int c = 0; c < 2; c++) {
                pa[c] = *reinterpret_cast<const float4*>(
                    A + (size_t)(row0 + lr[c]) * lda + kn + lc[c]);
                pw[c] = *reinterpret_cast<const float4*>(
                    W + (size_t)(col0 + lr[c]) * ldw + kn + lc[c]);
            }
        }

#pragma unroll
        for (int ks = 0; ks < 4; ks++) {
            const int kk = ks << 3;
            uint32_t af[2][4], bf[2][2];
#pragma unroll
            for (int mi = 0; mi < 2; mi++) {
                int r = wm + (mi << 4) + g;
                af[mi][0] = fu(Asb[buf][r][kk + tg]);
                af[mi][1] = fu(Asb[buf][r + 8][kk + tg]);
                af[mi][2] = fu(Asb[buf][r][kk + tg + 4]);
                af[mi][3] = fu(Asb[buf][r + 8][kk + tg + 4]);
            }
#pragma unroll
            for (int ni = 0; ni < 2; ni++) {
                int cn = wn + (ni << 3) + g;
                bf[ni][0] = fu(Wsb[buf][cn][kk + tg]);
                bf[ni][1] = fu(Wsb[buf][cn][kk + tg + 4]);
            }
#pragma unroll
            for (int mi = 0; mi < 2; mi++)
#pragma unroll
                for (int ni = 0; ni < 2; ni++)
                    mma_tf32(acc[mi][ni], af[mi], bf[ni]);
        }
        buf ^= 1;
    }

#pragma unroll
    for (int mi = 0; mi < 2; mi++) {
#pragma unroll
        for (int ni = 0; ni < 2; ni++) {
            int col = col0 + wn + (ni << 3) + (tg << 1);
            float b0 = 0.f, b1 = 0.f;
            if (BIAS) { b0 = bias[col]; b1 = bias[col + 1]; }
            int r0 = row0 + wm + (mi << 4) + g;
            int r1 = r0 + 8;
            *reinterpret_cast<float2*>(C + (size_t)r0 * ldc + col) =
                make_float2(acc[mi][ni][0] + b0, acc[mi][ni][1] + b1);
            *reinterpret_cast<float2*>(C + (size_t)r1 * ldc + col) =
                make_float2(acc[mi][ni][2] + b0, acc[mi][ni][3] + b1);
        }
    }
}

// ---------------------------------------------------------------------------
// K1: qproj + kproj. 256 blocks x 256 thr.
// ---------------------------------------------------------------------------
__global__ void __launch_bounds__(256) k1_proj(
    const float* __restrict__ query, const float* __restrict__ memory,
    const float* __restrict__ Wq, const float* __restrict__ bq,
    const float* __restrict__ Wk, const float* __restrict__ bk)
{
    __shared__ float As[2][64][36];
    __shared__ float Ws[2][64][36];
    const int t = blockIdx.x & 127;
    const int row0 = (t >> 3) << 6;
    const int col0 = (t & 7) << 6;
    if (blockIdx.x < 128)
        gemm_nt_256<true>(As, Ws, row0, col0, query, DQS, Wq, DQS, bq,
                          g_qproj, HH, DQS);
    else
        gemm_nt_256<true>(As, Ws, row0, col0, memory, DKS, Wk, DKS, bk,
                          g_kproj, HH, DKS);
}

// ---------------------------------------------------------------------------
// Scores body (f32 tanh.approx — round-6 proven). Writes MASKED logits.
// 256 thr = 8 warps; warp owns one q-row, block covers 8 q-rows x 64 m.
// ---------------------------------------------------------------------------
__device__ __forceinline__ void scores_body(int bid, float (*ks)[512],
                                            const float* __restrict__ Wl,
                                            const unsigned int* __restrict__ mask)
{
    const int b  = bid >> 7;
    const int qg = (bid >> 2) & 31;
    const int mg = bid & 3;
    const int q0 = qg << 3;
    const int m0base = mg << 6;

    const int tid = threadIdx.x;
    const int lane = tid & 31;
    const int w = tid >> 5;
    const int q = q0 + w;

    float qr[16], wl[16];
    const float* qp = g_qproj + ((size_t)(b * QQ + q)) * HH;
#pragma unroll
    for (int j = 0; j < 16; j++) {
        qr[j] = qp[lane + 32 * j];
        wl[j] = Wl[lane + 32 * j];
    }

    float* lout = g_logits + ((size_t)(b * QQ + q)) * MMM;
    const unsigned int* mrow = mask + b * MMM;

    for (int t = 0; t < 4; t++) {
        const int m0 = m0base + (t << 4);
        __syncthreads();
        const float* kp = g_kproj + ((size_t)(b * MMM + m0)) * HH;
#pragma unroll
        for (int i = 0; i < 8; i++) {
            int idx = tid + (i << 8);
            int mm = idx >> 7;
            int c4 = (idx & 127) << 2;
            *reinterpret_cast<float4*>(&ks[mm][c4]) =
                *reinterpret_cast<const float4*>(kp + mm * HH + c4);
        }
        __syncthreads();

#pragma unroll 4
        for (int mm = 0; mm < 16; mm++) {
            float acc = 0.f;
#pragma unroll
            for (int j = 0; j < 16; j++) {
                float s = qr[j] + ks[mm][lane + 32 * j];
                float th;
                asm("tanh.approx.f32 %0, %1;" : "=f"(th) : "f"(s));
                acc = fmaf(wl[j], th, acc);
            }
#pragma unroll
            for (int o = 16; o > 0; o >>= 1)
                acc += __shfl_xor_sync(0xFFFFFFFFu, acc, o);
            if (lane == 0)
                lout[m0 + mm] = (mrow[m0 + mm] != 0u) ? -1e18f : acc;
        }
    }
}

// ---------------------------------------------------------------------------
// K2: scores (512) + partial=query@Wo1^T+bo (128) + P2=memory@Wo2^T (128).
// ---------------------------------------------------------------------------
__global__ void __launch_bounds__(256) k2_scores_fused(
    const float* __restrict__ query, const float* __restrict__ memory,
    const float* __restrict__ Wo, const float* __restrict__ bo,
    const float* __restrict__ Wl, const unsigned int* __restrict__ mask)
{
    __shared__ __align__(16) union {
        float ks[16][512];                                   // 32 KB
        struct { float As[2][64][36]; float Ws[2][64][36]; } g;  // 36.9 KB
    } sm;

    const int bid = blockIdx.x;
    if (bid < 512) {
        scores_body(bid, sm.ks, Wl, mask);
    } else if (bid < 640) {
        const int t = bid - 512;
        gemm_nt_256<true>(sm.g.As, sm.g.Ws, (t >> 3) << 6, (t & 7) << 6,
                          query, DQS, Wo, DC, bo, g_partial, DQS, DQS);
    } else {
        const int t = bid - 640;
        gemm_nt_256<false>(sm.g.As, sm.g.Ws, (t >> 3) << 6, (t & 7) << 6,
                           memory, DKS, Wo + DQS, DC, nullptr, g_P2, DQS, DKS);
    }
}

// ---------------------------------------------------------------------------
// K4: fused softmax + final GEMM.  out = tanh(partial + softmax(L) @ P2)
// Softmax is applied ONCE per element at the smem STAGING store (where the
// tf32 cvt already lives), never in the fragment path.
// Each block also writes its own 32-wide m-slice of the weights output.
// 128 blocks x 256 thr, 64x64 tile, BK=32, double-buffered.
// ---------------------------------------------------------------------------
__global__ void __launch_bounds__(256) k4_final(
    float* __restrict__ out, float* __restrict__ weights)
{
    const int bid = blockIdx.x;
    const int b = bid >> 5;
    const int tile = bid & 31;
    const int row0 = (tile >> 3) << 6;   // q-tile
    const int ct   = tile & 7;           // o-tile index (also picks m-slice)
    const int col0 = ct << 6;

    const float* L  = g_logits + ((size_t)(b * QQ) + row0) * MMM;  // 64 x 256
    const float* Bm = g_P2 + (size_t)b * MMM * DQS;

    __shared__ float As[2][64][36];
    __shared__ float Bs[2][32][72];
    __shared__ float row_c[64];    // -max * log2e
    __shared__ float row_inv[64];  // 1 / sum

    const int tid  = threadIdx.x;
    const int lane = tid & 31;
    const int g    = lane >> 2;
    const int tg   = lane & 3;
    const int w    = tid >> 5;
    const int wm   = (w >> 2) << 5;
    const int wn   = (w & 3) << 4;

    const float LOG2E = 1.4426950408889634f;

    // ---- softmax stats: warp w handles rows w*8 .. w*8+7 ----
    for (int rr = 0; rr < 8; rr++) {
        int r = (w << 3) + rr;
        const float* lp = L + (size_t)r * MMM;
        float v[8];
        float mx = -3.4e38f;
#pragma unroll
        for (int j = 0; j < 8; j++) {
            v[j] = lp[lane + 32 * j];
            mx = fmaxf(mx, v[j]);
        }
#pragma unroll
        for (int o = 16; o > 0; o >>= 1)
            mx = fmaxf(mx, __shfl_xor_sync(0xFFFFFFFFu, mx, o));
        float s = 0.f;
#pragma unroll
        for (int j = 0; j < 8; j++) s += __expf(v[j] - mx);
#pragma unroll
        for (int o = 16; o > 0; o >>= 1)
            s += __shfl_xor_sync(0xFFFFFFFFu, s, o);
        if (lane == 0) {
            row_c[r]   = -mx * LOG2E;
            row_inv[r] = 1.f / s;
        }
    }
    __syncthreads();

    // ---- weights output: this block writes m-slice [ct*32, ct*32+32) ----
    {
        int m = (ct << 5) + lane;
        for (int rr = 0; rr < 8; rr++) {
            int r = (w << 3) + rr;
            float x = L[(size_t)r * MMM + m];
            weights[((size_t)(b * QQ) + row0 + r) * MMM + m] =
                exp2f(fmaf(x, LOG2E, row_c[r])) * row_inv[r];
        }
    }

    // ---- loaders + per-loader row constants ----
    int la_r[2], la_c[2], lb_r[2], lb_c[2];
    float lrc[2], lri[2];
#pragma unroll
    for (int c = 0; c < 2; c++) {
        int idx = tid + (c << 8);
        la_r[c] = idx >> 3;  la_c[c] = (idx & 7) << 2;    // A: 64 x 8 f4
        lb_r[c] = idx >> 4;  lb_c[c] = (idx & 15) << 2;   // B: 32 x 16 f4
        lrc[c] = row_c[la_r[c]];
        lri[c] = row_inv[la_r[c]];
    }

    float acc[2][2][4];
#pragma unroll
    for (int mi = 0; mi < 2; mi++)
#pragma unroll
        for (int ni = 0; ni < 2; ni++)
#pragma unroll
            for (int j = 0; j < 4; j++) acc[mi][ni][j] = 0.f;

    float4 pa[2], pb[2];
#pragma unroll
    for (int c = 0; c < 2; c++) {
        pa[c] = *reinterpret_cast<const float4*>(L + (size_t)la_r[c] * MMM + la_c[c]);
        pb[c] = *reinterpret_cast<const float4*>(Bm + (size_t)lb_r[c] * DQS + col0 + lb_c[c]);
    }

    int buf = 0;
    for (int k0 = 0; k0 < MMM; k0 += 32) {
#pragma unroll
        for (int c = 0; c < 2; c++) {
            float4 va = pa[c], vb = pb[c];
            // softmax + cvt at the store (once per element)
            float w0 = exp2f(fmaf(va.x, LOG2E, lrc[c])) * lri[c];
            float w1 = exp2f(fmaf(va.y, LOG2E, lrc[c])) * lri[c];
            float w2 = exp2f(fmaf(va.z, LOG2E, lrc[c])) * lri[c];
            float w3 = exp2f(fmaf(va.w, LOG2E, lrc[c])) * lri[c];
            *reinterpret_cast<float4*>(&As[buf][la_r[c]][la_c[c]]) =
                make_float4(f2tf32(w0), f2tf32(w1), f2tf32(w2), f2tf32(w3));
            *reinterpret_cast<float4*>(&Bs[buf][lb_r[c]][lb_c[c]]) =
                make_float4(f2tf32(vb.x), f2tf32(vb.y), f2tf32(vb.z), f2tf32(vb.w));
        }
        __syncthreads();

        int kn = k0 + 32;
        if (kn < MMM) {
#pragma unroll
            for (int c = 0; c < 2; c++) {
                pa[c] = *reinterpret_cast<const float4*>(
                    L + (size_t)la_r[c] * MMM + kn + la_c[c]);
                pb[c] = *reinterpret_cast<const float4*>(
                    Bm + (size_t)(kn + lb_r[c]) * DQS + col0 + lb_c[c]);
            }
        }

#pragma unroll
        for (int ks = 0; ks < 4; ks++) {
            const int kk = ks << 3;
            uint32_t af[2][4], bf[2][2];
#pragma unroll
            for (int mi = 0; mi < 2; mi++) {
                int r = wm + (mi << 4) + g;
                af[mi][0] = fu(As[buf][r][kk + tg]);
                af[mi][1] = fu(As[buf][r + 8][kk + tg]);
                af[mi][2] = fu(As[buf][r][kk + tg + 4]);
                af[mi][3] = fu(As[buf][r + 8][kk + tg + 4]);
            }
#pragma unroll
            for (int ni = 0; ni < 2; ni++) {
                int cn = wn + (ni << 3) + g;
                bf[ni][0] = fu(Bs[buf][kk + tg][cn]);
                bf[ni][1] = fu(Bs[buf][kk + tg + 4][cn]);
            }
#pragma unroll
            for (int mi = 0; mi < 2; mi++)
#pragma unroll
                for (int ni = 0; ni < 2; ni++)
                    mma_tf32(acc[mi][ni], af[mi], bf[ni]);
        }
        buf ^= 1;
    }

    // ---- epilogue: tanh(acc + partial) ----
#pragma unroll
    for (int mi = 0; mi < 2; mi++) {
#pragma unroll
        for (int ni = 0; ni < 2; ni++) {
            int col = col0 + wn + (ni << 3) + (tg << 1);
            size_t r0 = (size_t)b * QQ + row0 + wm + (mi << 4) + g;
            size_t r1 = r0 + 8;
            float2 p0 = *reinterpret_cast<const float2*>(&g_partial[r0 * DQS + col]);
            float2 p1 = *reinterpret_cast<const float2*>(&g_partial[r1 * DQS + col]);
            *reinterpret_cast<float2*>(out + r0 * DQS + col) =
                make_float2(tanhf(acc[mi][ni][0] + p0.x), tanhf(acc[mi][ni][1] + p0.y));
            *reinterpret_cast<float2*>(out + r1 * DQS + col) =
                make_float2(tanhf(acc[mi][ni][2] + p1.x), tanhf(acc[mi][ni][3] + p1.y));
        }
    }
}

// ---------------------------------------------------------------------------
// Launch
// ---------------------------------------------------------------------------
extern "C" void kernel_launch(void* const* d_in, const int* in_sizes, int n_in,
                              void* d_out, int out_size)
{
    const float* query  = (const float*)d_in[0];
    const float* memory = (const float*)d_in[1];
    const unsigned int* mask = (const unsigned int*)d_in[2];
    const float* Wk = (const float*)d_in[3];
    const float* bk = (const float*)d_in[4];
    const float* Wq = (const float*)d_in[5];
    const float* bq = (const float*)d_in[6];
    const float* Wl = (const float*)d_in[7];
    // d_in[8] = bl (uniform shift — cancels in softmax)
    const float* Wo = (const float*)d_in[9];
    const float* bo = (const float*)d_in[10];

    float* out     = (float*)d_out;
    float* weights = out + BB * QQ * DQS;

    k1_proj<<<256, 256>>>(query, memory, Wq, bq, Wk, bk);
    k2_scores_fused<<<768, 256>>>(query, memory, Wo, bo, Wl, mask);
    k4_final<<<128, 256>>>(out, weights);
}

// round 12
// speedup vs baseline: 1.1190x; 1.0476x over previous
#include <cuda_runtime.h>
#include <stdint.h>

#define BB 4
#define QQ 256
#define MMM 256
#define HH 512
#define DQS 512
#define DKS 512
#define DC (DQS + DKS)

// Scratch device globals
__device__ float g_qproj[BB * QQ * HH];    // 2 MB
__device__ float g_kproj[BB * MMM * HH];   // 2 MB
__device__ float g_logits[BB * QQ * MMM];  // 1 MB (raw logits; k3 masks)
__device__ float g_partial[BB * QQ * DQS]; // 2 MB  query @ Wo1^T + bo
__device__ float g_P2[BB * MMM * DQS];     // 2 MB  memory @ Wo2^T

// ---------------------------------------------------------------------------
// helpers
// ---------------------------------------------------------------------------
__device__ __forceinline__ float f2tf32(float x) {
    uint32_t r;
    asm("cvt.rna.tf32.f32 %0, %1;" : "=r"(r) : "f"(x));
    return __uint_as_float(r);
}
__device__ __forceinline__ uint32_t fu(float x) { return __float_as_uint(x); }

__device__ __forceinline__ void mma_tf32(float c[4], const uint32_t a[4],
                                         const uint32_t b[2]) {
    asm volatile(
        "mma.sync.aligned.m16n8k8.row.col.f32.tf32.tf32.f32 "
        "{%0,%1,%2,%3}, {%4,%5,%6,%7}, {%8,%9}, {%0,%1,%2,%3};"
        : "+f"(c[0]), "+f"(c[1]), "+f"(c[2]), "+f"(c[3])
        : "r"(a[0]), "r"(a[1]), "r"(a[2]), "r"(a[3]), "r"(b[0]), "r"(b[1]));
}

__device__ __forceinline__ uint32_t smem_u32(const void* p) {
    return (uint32_t)__cvta_generic_to_shared(p);
}
__device__ __forceinline__ void cp_async16(uint32_t dst, const void* src) {
    asm volatile("cp.async.cg.shared.global [%0], [%1], 16;" :: "r"(dst), "l"(src));
}
__device__ __forceinline__ void cp_commit() {
    asm volatile("cp.async.commit_group;");
}
template<int N> __device__ __forceinline__ void cp_wait() {
    asm volatile("cp.async.wait_group %0;" :: "n"(N));
}

// ---------------------------------------------------------------------------
// K1: qproj + kproj (NT), cp.async 2-stage, 64x64 tile, BK=32, 256 thr.
// (round-9 version — measured 20.8us vs 23.1 for reg-prefetch variant)
// ---------------------------------------------------------------------------
__device__ __forceinline__ void gemm_nt_cp(
    float (*As)[64][36], float (*Ws)[64][36],
    int row0, int col0,
    const float* __restrict__ A, int lda,
    const float* __restrict__ W, int ldw,
    const float* __restrict__ bias,
    float* __restrict__ C, int ldc, int K)
{
    const int tid  = threadIdx.x;
    const int lane = tid & 31;
    const int g    = lane >> 2;
    const int tg   = lane & 3;
    const int w    = tid >> 5;
    const int wm   = (w >> 2) << 5;
    const int wn   = (w & 3) << 4;

    int lr[2], lc[2];
#pragma unroll
    for (int c = 0; c < 2; c++) {
        int idx = tid + (c << 8);
        lr[c] = idx >> 3;
        lc[c] = (idx & 7) << 2;
    }

    const int nk = K >> 5;

#pragma unroll
    for (int c = 0; c < 2; c++) {
        cp_async16(smem_u32(&As[0][lr[c]][lc[c]]),
                   A + (size_t)(row0 + lr[c]) * lda + lc[c]);
        cp_async16(smem_u32(&Ws[0][lr[c]][lc[c]]),
                   W + (size_t)(col0 + lr[c]) * ldw + lc[c]);
    }
    cp_commit();

    float acc[2][2][4];
#pragma unroll
    for (int mi = 0; mi < 2; mi++)
#pragma unroll
        for (int ni = 0; ni < 2; ni++)
#pragma unroll
            for (int j = 0; j < 4; j++) acc[mi][ni][j] = 0.f;

    for (int i = 0; i < nk; i++) {
        cp_wait<0>();
        __syncthreads();
        if (i + 1 < nk) {
            int kn = (i + 1) << 5;
            int nb = (i + 1) & 1;
#pragma unroll
            for (int c = 0; c < 2; c++) {
                cp_async16(smem_u32(&As[nb][lr[c]][lc[c]]),
                           A + (size_t)(row0 + lr[c]) * lda + kn + lc[c]);
                cp_async16(smem_u32(&Ws[nb][lr[c]][lc[c]]),
                           W + (size_t)(col0 + lr[c]) * ldw + kn + lc[c]);
            }
            cp_commit();
        }
        const int buf = i & 1;
#pragma unroll
        for (int ks = 0; ks < 4; ks++) {
            const int kk = ks << 3;
            uint32_t af[2][4], bf[2][2];
#pragma unroll
            for (int mi = 0; mi < 2; mi++) {
                int r = wm + (mi << 4) + g;
                af[mi][0] = fu(f2tf32(As[buf][r][kk + tg]));
                af[mi][1] = fu(f2tf32(As[buf][r + 8][kk + tg]));
                af[mi][2] = fu(f2tf32(As[buf][r][kk + tg + 4]));
                af[mi][3] = fu(f2tf32(As[buf][r + 8][kk + tg + 4]));
            }
#pragma unroll
            for (int ni = 0; ni < 2; ni++) {
                int cn = wn + (ni << 3) + g;
                bf[ni][0] = fu(f2tf32(Ws[buf][cn][kk + tg]));
                bf[ni][1] = fu(f2tf32(Ws[buf][cn][kk + tg + 4]));
            }
#pragma unroll
            for (int mi = 0; mi < 2; mi++)
#pragma unroll
                for (int ni = 0; ni < 2; ni++)
                    mma_tf32(acc[mi][ni], af[mi], bf[ni]);
        }
    }

#pragma unroll
    for (int mi = 0; mi < 2; mi++) {
#pragma unroll
        for (int ni = 0; ni < 2; ni++) {
            int col = col0 + wn + (ni << 3) + (tg << 1);
            float b0 = bias ? bias[col] : 0.f;
            float b1 = bias ? bias[col + 1] : 0.f;
            int r0 = row0 + wm + (mi << 4) + g;
            int r1 = r0 + 8;
            *reinterpret_cast<float2*>(C + (size_t)r0 * ldc + col) =
                make_float2(acc[mi][ni][0] + b0, acc[mi][ni][1] + b1);
            *reinterpret_cast<float2*>(C + (size_t)r1 * ldc + col) =
                make_float2(acc[mi][ni][2] + b0, acc[mi][ni][3] + b1);
        }
    }
}

__global__ void __launch_bounds__(256) k1_proj(
    const float* __restrict__ query, const float* __restrict__ memory,
    const float* __restrict__ Wq, const float* __restrict__ bq,
    const float* __restrict__ Wk, const float* __restrict__ bk)
{
    __shared__ float As[2][64][36];
    __shared__ float Ws[2][64][36];
    const int t = blockIdx.x & 127;
    const int row0 = (t >> 3) << 6;
    const int col0 = (t & 7) << 6;
    if (blockIdx.x < 128)
        gemm_nt_cp(As, Ws, row0, col0, query, DQS, Wq, DQS, bq, g_qproj, HH, DQS);
    else
        gemm_nt_cp(As, Ws, row0, col0, memory, DKS, Wk, DKS, bk, g_kproj, HH, DKS);
}

// ---------------------------------------------------------------------------
// NT tf32 GEMM body (round-6: reg prefetch, cvt at store) — k2 fused blocks.
// ---------------------------------------------------------------------------
template<bool BIAS>
__device__ __forceinline__ void gemm_nt_256(
    float (*Asb)[64][36], float (*Wsb)[64][36],
    int row0, int col0,
    const float* __restrict__ A, int lda,
    const float* __restrict__ W, int ldw,
    const float* __restrict__ bias,
    float* __restrict__ C, int ldc, int K)
{
    const int tid  = threadIdx.x;
    const int lane = tid & 31;
    const int g    = lane >> 2;
    const int tg   = lane & 3;
    const int w    = tid >> 5;
    const int wm   = (w >> 2) << 5;
    const int wn   = (w & 3) << 4;

    int lr[2], lc[2];
#pragma unroll
    for (int c = 0; c < 2; c++) {
        int idx = tid + (c << 8);
        lr[c] = idx >> 3;
        lc[c] = (idx & 7) << 2;
    }

    float acc[2][2][4];
#pragma unroll
    for (int mi = 0; mi < 2; mi++)
#pragma unroll
        for (int ni = 0; ni < 2; ni++)
#pragma unroll
            for (int j = 0; j < 4; j++) acc[mi][ni][j] = 0.f;

    float4 pa[2], pw[2];
#pragma unroll
    for (int c = 0; c < 2; c++) {
        pa[c] = *reinterpret_cast<const float4*>(A + (size_t)(row0 + lr[c]) * lda + lc[c]);
        pw[c] = *reinterpret_cast<const float4*>(W + (size_t)(col0 + lr[c]) * ldw + lc[c]);
    }

    int buf = 0;
    for (int k0 = 0; k0 < K; k0 += 32) {
#pragma unroll
        for (int c = 0; c < 2; c++) {
            float4 va = pa[c], vw = pw[c];
            *reinterpret_cast<float4*>(&Asb[buf][lr[c]][lc[c]]) =
                make_float4(f2tf32(va.x), f2tf32(va.y), f2tf32(va.z), f2tf32(va.w));
            *reinterpret_cast<float4*>(&Wsb[buf][lr[c]][lc[c]]) =
                make_float4(f2tf32(vw.x), f2tf32(vw.y), f2tf32(vw.z), f2tf32(vw.w));
        }
        __syncthreads();

        int kn = k0 + 32;
        if (kn < K) {
#pragma unroll
            for (int c = 0; c < 2; c++) {
                pa[c] = *reinterpret_cast<const float4*>(
                    A + (size_t)(row0 + lr[c]) * lda + kn + lc[c]);
                pw[c] = *reinterpret_cast<const float4*>(
                    W + (size_t)(col0 + lr[c]) * ldw + kn + lc[c]);
            }
        }

#pragma unroll
        for (int ks = 0; ks < 4; ks++) {
            const int kk = ks << 3;
            uint32_t af[2][4], bf[2][2];
#pragma unroll
            for (int mi = 0; mi < 2; mi++) {
                int r = wm + (mi << 4) + g;
                af[mi][0] = fu(Asb[buf][r][kk + tg]);
                af[mi][1] = fu(Asb[buf][r + 8][kk + tg]);
                af[mi][2] = fu(Asb[buf][r][kk + tg + 4]);
                af[mi][3] = fu(Asb[buf][r + 8][kk + tg + 4]);
            }
#pragma unroll
            for (int ni = 0; ni < 2; ni++) {
                int cn = wn + (ni << 3) + g;
                bf[ni][0] = fu(Wsb[buf][cn][kk + tg]);
                bf[ni][1] = fu(Wsb[buf][cn][kk + tg + 4]);
            }
#pragma unroll
            for (int mi = 0; mi < 2; mi++)
#pragma unroll
                for (int ni = 0; ni < 2; ni++)
                    mma_tf32(acc[mi][ni], af[mi], bf[ni]);
        }
        buf ^= 1;
    }

#pragma unroll
    for (int mi = 0; mi < 2; mi++) {
#pragma unroll
        for (int ni = 0; ni < 2; ni++) {
            int col = col0 + wn + (ni << 3) + (tg << 1);
            float b0 = 0.f, b1 = 0.f;
            if (BIAS) { b0 = bias[col]; b1 = bias[col + 1]; }
            int r0 = row0 + wm + (mi << 4) + g;
            int r1 = r0 + 8;
            *reinterpret_cast<float2*>(C + (size_t)r0 * ldc + col) =
                make_float2(acc[mi][ni][0] + b0, acc[mi][ni][1] + b1);
            *reinterpret_cast<float2*>(C + (size_t)r1 * ldc + col) =
                make_float2(acc[mi][ni][2] + b0, acc[mi][ni][3] + b1);
        }
    }
}

// ---------------------------------------------------------------------------
// Scores body (round-6: f32 tanh.approx, raw logits; k3 masks).
// ---------------------------------------------------------------------------
__device__ __forceinline__ void scores_body(int bid, float (*ks)[512],
                                            const float* __restrict__ Wl)
{
    const int b  = bid >> 7;
    const int qg = (bid >> 2) & 31;
    const int mg = bid & 3;
    const int q0 = qg << 3;
    const int m0base = mg << 6;

    const int tid = threadIdx.x;
    const int lane = tid & 31;
    const int w = tid >> 5;
    const int q = q0 + w;

    float qr[16], wl[16];
    const float* qp = g_qproj + ((size_t)(b * QQ + q)) * HH;
#pragma unroll
    for (int j = 0; j < 16; j++) {
        qr[j] = qp[lane + 32 * j];
        wl[j] = Wl[lane + 32 * j];
    }

    float* lout = g_logits + ((size_t)(b * QQ + q)) * MMM;

    for (int t = 0; t < 4; t++) {
        const int m0 = m0base + (t << 4);
        __syncthreads();
        const float* kp = g_kproj + ((size_t)(b * MMM + m0)) * HH;
#pragma unroll
        for (int i = 0; i < 8; i++) {
            int idx = tid + (i << 8);
            int mm = idx >> 7;
            int c4 = (idx & 127) << 2;
            *reinterpret_cast<float4*>(&ks[mm][c4]) =
                *reinterpret_cast<const float4*>(kp + mm * HH + c4);
        }
        __syncthreads();

#pragma unroll 4
        for (int mm = 0; mm < 16; mm++) {
            float acc = 0.f;
#pragma unroll
            for (int j = 0; j < 16; j++) {
                float s = qr[j] + ks[mm][lane + 32 * j];
                float th;
                asm("tanh.approx.f32 %0, %1;" : "=f"(th) : "f"(s));
                acc = fmaf(wl[j], th, acc);
            }
#pragma unroll
            for (int o = 16; o > 0; o >>= 1)
                acc += __shfl_xor_sync(0xFFFFFFFFu, acc, o);
            if (lane == 0) lout[m0 + mm] = acc;
        }
    }
}

// ---------------------------------------------------------------------------
// K2: scores (512) + partial=query@Wo1^T+bo (128) + P2=memory@Wo2^T (128).
// ---------------------------------------------------------------------------
__global__ void __launch_bounds__(256) k2_scores_fused(
    const float* __restrict__ query, const float* __restrict__ memory,
    const float* __restrict__ Wo, const float* __restrict__ bo,
    const float* __restrict__ Wl)
{
    __shared__ __align__(16) union {
        float ks[16][512];
        struct { float As[2][64][36]; float Ws[2][64][36]; } g;
    } sm;

    const int bid = blockIdx.x;
    if (bid < 512) {
        scores_body(bid, sm.ks, Wl);
    } else if (bid < 640) {
        const int t = bid - 512;
        gemm_nt_256<true>(sm.g.As, sm.g.Ws, (t >> 3) << 6, (t & 7) << 6,
                          query, DQS, Wo, DC, bo, g_partial, DQS, DQS);
    } else {
        const int t = bid - 640;
        gemm_nt_256<false>(sm.g.As, sm.g.Ws, (t >> 3) << 6, (t & 7) << 6,
                           memory, DKS, Wo + DQS, DC, nullptr, g_P2, DQS, DKS);
    }
}

// ---------------------------------------------------------------------------
// K3: softmax + mask (round-6). 256 blocks x 128 threads, warp per q-row.
// ---------------------------------------------------------------------------
__global__ void __launch_bounds__(128) k3_softmax(
    const unsigned int* __restrict__ mask,
    float* __restrict__ weights)
{
    const int bid = blockIdx.x;
    const int b = bid >> 6;
    const int lane = threadIdx.x & 31;
    const int w = threadIdx.x >> 5;
    const int q = ((bid & 63) << 2) + w;

    const float* lin = g_logits + ((size_t)(b * QQ + q)) * MMM;
    const unsigned int* mrow = mask + b * MMM;

    float v[8];
    float mx = -3.4e38f;
#pragma unroll
    for (int j = 0; j < 8; j++) {
        int m = lane + 32 * j;
        float s = lin[m];
        if (mrow[m] != 0u) s = -1e18f;
        v[j] = s;
        mx = fmaxf(mx, s);
    }
#pragma unroll
    for (int o = 16; o > 0; o >>= 1)
        mx = fmaxf(mx, __shfl_xor_sync(0xFFFFFFFFu, mx, o));
    float sum = 0.f;
#pragma unroll
    for (int j = 0; j < 8; j++) {
        v[j] = __expf(v[j] - mx);
        sum += v[j];
    }
#pragma unroll
    for (int o = 16; o > 0; o >>= 1)
        sum += __shfl_xor_sync(0xFFFFFFFFu, sum, o);
    float inv = 1.f / sum;

    float* wout = weights + ((size_t)(b * QQ + q)) * MMM;
#pragma unroll
    for (int j = 0; j < 8; j++)
        wout[lane + 32 * j] = v[j] * inv;
}

// ---------------------------------------------------------------------------
// K4: out = tanh(partial + weights @ P2). Round-5 128-thr/32x32 shape
// (measured 11.2us analog vs 13.0 for 256-thr shape). 128 blocks.
// ---------------------------------------------------------------------------
__global__ void __launch_bounds__(128) k4_final(
    const float* __restrict__ Wt, float* __restrict__ out)
{
    const int bid = blockIdx.x;
    const int b = bid >> 5;
    const int tile = bid & 31;
    const int row0 = (tile >> 3) << 6;
    const int col0 = (tile & 7) << 6;

    const float* A  = Wt   + (size_t)b * QQ * MMM;
    const float* Bm = g_P2 + (size_t)b * MMM * DQS;

    __shared__ float As[64][36];
    __shared__ float Bs[32][72];

    const int tid  = threadIdx.x;
    const int lane = tid & 31;
    const int g    = lane >> 2;
    const int tg   = lane & 3;
    const int w    = tid >> 5;
    const int wm   = (w >> 1) << 5;
    const int wn   = (w & 1) << 5;

    int ar[4], ac[4], br[4], bc[4];
#pragma unroll
    for (int c = 0; c < 4; c++) {
        int idx = tid + (c << 7);
        ar[c] = idx >> 3;  ac[c] = (idx & 7) << 2;
        br[c] = idx >> 4;  bc[c] = (idx & 15) << 2;
    }

    float acc[2][4][4];
#pragma unroll
    for (int mi = 0; mi < 2; mi++)
#pragma unroll
        for (int ni = 0; ni < 4; ni++)
#pragma unroll
            for (int j = 0; j < 4; j++) acc[mi][ni][j] = 0.f;

    float4 pa[4], pb[4];
#pragma unroll
    for (int c = 0; c < 4; c++) {
        pa[c] = *reinterpret_cast<const float4*>(A + (size_t)(row0 + ar[c]) * MMM + ac[c]);
        pb[c] = *reinterpret_cast<const float4*>(Bm + (size_t)br[c] * DQS + col0 + bc[c]);
    }

    for (int k0 = 0; k0 < MMM; k0 += 32) {
#pragma unroll
        for (int c = 0; c < 4; c++) {
            float4 va = pa[c], vb = pb[c];
            *reinterpret_cast<float4*>(&As[ar[c]][ac[c]]) =
                make_float4(f2tf32(va.x), f2tf32(va.y), f2tf32(va.z), f2tf32(va.w));
            *reinterpret_cast<float4*>(&Bs[br[c]][bc[c]]) =
                make_float4(f2tf32(vb.x), f2tf32(vb.y), f2tf32(vb.z), f2tf32(vb.w));
        }
        __syncthreads();

        int kn = k0 + 32;
        if (kn < MMM) {
#pragma unroll
            for (int c = 0; c < 4; c++) {
                pa[c] = *reinterpret_cast<const float4*>(
                    A + (size_t)(row0 + ar[c]) * MMM + kn + ac[c]);
                pb[c] = *reinterpret_cast<const float4*>(
                    Bm + (size_t)(kn + br[c]) * DQS + col0 + bc[c]);
            }
        }

#pragma unroll
        for (int ks = 0; ks < 4; ks++) {
            const int kk = ks << 3;
            uint32_t af[2][4], bf[4][2];
#pragma unroll
            for (int mi = 0; mi < 2; mi++) {
                int r = wm + (mi << 4) + g;
                af[mi][0] = fu(As[r][kk + tg]);
                af[mi][1] = fu(As[r + 8][kk + tg]);
                af[mi][2] = fu(As[r][kk + tg + 4]);
                af[mi][3] = fu(As[r + 8][kk + tg + 4]);
            }
#pragma unroll
            for (int ni = 0; ni < 4; ni++) {
                int cn = wn + (ni << 3) + g;
                bf[ni][0] = fu(Bs[kk + tg][cn]);
                bf[ni][1] = fu(Bs[kk + tg + 4][cn]);
            }
#pragma unroll
            for (int mi = 0; mi < 2; mi++)
#pragma unroll
                for (int ni = 0; ni < 4; ni++)
                    mma_tf32(acc[mi][ni], af[mi], bf[ni]);
        }
        __syncthreads();
    }

#pragma unroll
    for (int mi = 0; mi < 2; mi++) {
#pragma unroll
        for (int ni = 0; ni < 4; ni++) {
            int col = col0 + wn + (ni << 3) + (tg << 1);
            size_t r0 = (size_t)b * QQ + row0 + wm + (mi << 4) + g;
            size_t r1 = r0 + 8;
            float2 p0 = *reinterpret_cast<const float2*>(&g_partial[r0 * DQS + col]);
            float2 p1 = *reinterpret_cast<const float2*>(&g_partial[r1 * DQS + col]);
            *reinterpret_cast<float2*>(out + r0 * DQS + col) =
                make_float2(tanhf(acc[mi][ni][0] + p0.x), tanhf(acc[mi][ni][1] + p0.y));
            *reinterpret_cast<float2*>(out + r1 * DQS + col) =
                make_float2(tanhf(acc[mi][ni][2] + p1.x), tanhf(acc[mi][ni][3] + p1.y));
        }
    }
}

// ---------------------------------------------------------------------------
// Launch
// ---------------------------------------------------------------------------
extern "C" void kernel_launch(void* const* d_in, const int* in_sizes, int n_in,
                              void* d_out, int out_size)
{
    const float* query  = (const float*)d_in[0];
    const float* memory = (const float*)d_in[1];
    const unsigned int* mask = (const unsigned int*)d_in[2];
    const float* Wk = (const float*)d_in[3];
    const float* bk = (const float*)d_in[4];
    const float* Wq = (const float*)d_in[5];
    const float* bq = (const float*)d_in[6];
    const float* Wl = (const float*)d_in[7];
    // d_in[8] = bl (uniform shift — cancels in softmax)
    const float* Wo = (const float*)d_in[9];
    const float* bo = (const float*)d_in[10];

    float* out     = (float*)d_out;
    float* weights = out + BB * QQ * DQS;

    k1_proj<<<256, 256>>>(query, memory, Wq, bq, Wk, bk);
    k2_scores_fused<<<768, 256>>>(query, memory, Wo, bo, Wl);
    k3_softmax<<<256, 128>>>(mask, weights);
    k4_final<<<128, 128>>>(weights, out);
}

// round 14
// speedup vs baseline: 1.1759x; 1.0508x over previous
#include <cuda_runtime.h>
#include <stdint.h>

#define BB 4
#define QQ 256
#define MMM 256
#define HH 512
#define DQS 512
#define DKS 512
#define DC (DQS + DKS)

// Scratch device globals
__device__ float g_qproj[BB * QQ * HH];    // 2 MB
__device__ float g_kproj[BB * MMM * HH];   // 2 MB
__device__ float g_logits[BB * QQ * MMM];  // 1 MB (raw logits; k3 masks)
__device__ float g_partial[BB * QQ * DQS]; // 2 MB  query @ Wo1^T + bo
__device__ float g_P2[BB * MMM * DQS];     // 2 MB  memory @ Wo2^T

// ---------------------------------------------------------------------------
// helpers
// ---------------------------------------------------------------------------
__device__ __forceinline__ float f2tf32(float x) {
    uint32_t r;
    asm("cvt.rna.tf32.f32 %0, %1;" : "=r"(r) : "f"(x));
    return __uint_as_float(r);
}
__device__ __forceinline__ uint32_t fu(float x) { return __float_as_uint(x); }

__device__ __forceinline__ void mma_tf32(float c[4], const uint32_t a[4],
                                         const uint32_t b[2]) {
    asm volatile(
        "mma.sync.aligned.m16n8k8.row.col.f32.tf32.tf32.f32 "
        "{%0,%1,%2,%3}, {%4,%5,%6,%7}, {%8,%9}, {%0,%1,%2,%3};"
        : "+f"(c[0]), "+f"(c[1]), "+f"(c[2]), "+f"(c[3])
        : "r"(a[0]), "r"(a[1]), "r"(a[2]), "r"(a[3]), "r"(b[0]), "r"(b[1]));
}

// ---------------------------------------------------------------------------
// NT tf32 GEMM body (round-6 measured-80us version: single smem buffer,
// register prefetch, cvt at store). 256 threads, 64x64 tile, BK=32.
// 8 warps (2x4), warp tile 32x16. Stride 36 -> conflict-free fragment LDS.
// ---------------------------------------------------------------------------
template<bool BIAS>
__device__ __forceinline__ void gemm_nt_256(
    float (*As)[36], float (*Ws)[36],
    int row0, int col0,
    const float* __restrict__ A, int lda,
    const float* __restrict__ W, int ldw,
    const float* __restrict__ bias,
    float* __restrict__ C, int ldc, int K)
{
    const int tid  = threadIdx.x;
    const int lane = tid & 31;
    const int g    = lane >> 2;
    const int tg   = lane & 3;
    const int w    = tid >> 5;
    const int wm   = (w >> 2) << 5;
    const int wn   = (w & 3) << 4;

    int lr[2], lc[2];
#pragma unroll
    for (int c = 0; c < 2; c++) {
        int idx = tid + (c << 8);
        lr[c] = idx >> 3;
        lc[c] = (idx & 7) << 2;
    }

    float acc[2][2][4];
#pragma unroll
    for (int mi = 0; mi < 2; mi++)
#pragma unroll
        for (int ni = 0; ni < 2; ni++)
#pragma unroll
            for (int j = 0; j < 4; j++) acc[mi][ni][j] = 0.f;

    float4 pa[2], pw[2];
#pragma unroll
    for (int c = 0; c < 2; c++) {
        pa[c] = *reinterpret_cast<const float4*>(A + (size_t)(row0 + lr[c]) * lda + lc[c]);
        pw[c] = *reinterpret_cast<const float4*>(W + (size_t)(col0 + lr[c]) * ldw + lc[c]);
    }

    for (int k0 = 0; k0 < K; k0 += 32) {
#pragma unroll
        for (int c = 0; c < 2; c++) {
            float4 va = pa[c], vw = pw[c];
            *reinterpret_cast<float4*>(&As[lr[c]][lc[c]]) =
                make_float4(f2tf32(va.x), f2tf32(va.y), f2tf32(va.z), f2tf32(va.w));
            *reinterpret_cast<float4*>(&Ws[lr[c]][lc[c]]) =
                make_float4(f2tf32(vw.x), f2tf32(vw.y), f2tf32(vw.z), f2tf32(vw.w));
        }
        __syncthreads();

        int kn = k0 + 32;
        if (kn < K) {
#pragma unroll
            for (int c = 0; c < 2; c++) {
                pa[c] = *reinterpret_cast<const float4*>(
                    A + (size_t)(row0 + lr[c]) * lda + kn + lc[c]);
                pw[c] = *reinterpret_cast<const float4*>(
                    W + (size_t)(col0 + lr[c]) * ldw + kn + lc[c]);
            }
        }

#pragma unroll
        for (int ks = 0; ks < 4; ks++) {
            const int kk = ks << 3;
            uint32_t af[2][4], bf[2][2];
#pragma unroll
            for (int mi = 0; mi < 2; mi++) {
                int r = wm + (mi << 4) + g;
                af[mi][0] = fu(As[r][kk + tg]);
                af[mi][1] = fu(As[r + 8][kk + tg]);
                af[mi][2] = fu(As[r][kk + tg + 4]);
                af[mi][3] = fu(As[r + 8][kk + tg + 4]);
            }
#pragma unroll
            for (int ni = 0; ni < 2; ni++) {
                int cn = wn + (ni << 3) + g;
                bf[ni][0] = fu(Ws[cn][kk + tg]);
                bf[ni][1] = fu(Ws[cn][kk + tg + 4]);
            }
#pragma unroll
            for (int mi = 0; mi < 2; mi++)
#pragma unroll
                for (int ni = 0; ni < 2; ni++)
                    mma_tf32(acc[mi][ni], af[mi], bf[ni]);
        }
        __syncthreads();
    }

#pragma unroll
    for (int mi = 0; mi < 2; mi++) {
#pragma unroll
        for (int ni = 0; ni < 2; ni++) {
            int col = col0 + wn + (ni << 3) + (tg << 1);
            float b0 = 0.f, b1 = 0.f;
            if (BIAS) { b0 = bias[col]; b1 = bias[col + 1]; }
            int r0 = row0 + wm + (mi << 4) + g;
            int r1 = r0 + 8;
            *reinterpret_cast<float2*>(C + (size_t)r0 * ldc + col) =
                make_float2(acc[mi][ni][0] + b0, acc[mi][ni][1] + b1);
            *reinterpret_cast<float2*>(C + (size_t)r1 * ldc + col) =
                make_float2(acc[mi][ni][2] + b0, acc[mi][ni][3] + b1);
        }
    }
}

// ---------------------------------------------------------------------------
// K1: qproj + kproj. 256 blocks x 256 thr (round-6 exact).
// ---------------------------------------------------------------------------
__global__ void __launch_bounds__(256) k1_proj(
    const float* __restrict__ query, const float* __restrict__ memory,
    const float* __restrict__ Wq, const float* __restrict__ bq,
    const float* __restrict__ Wk, const float* __restrict__ bk)
{
    __shared__ float As[64][36];
    __shared__ float Ws[64][36];
    const int t = blockIdx.x & 127;
    const int row0 = (t >> 3) << 6;
    const int col0 = (t & 7) << 6;
    if (blockIdx.x < 128)
        gemm_nt_256<true>(As, Ws, row0, col0, query, DQS, Wq, DQS, bq,
                          g_qproj, HH, DQS);
    else
        gemm_nt_256<true>(As, Ws, row0, col0, memory, DKS, Wk, DKS, bk,
                          g_kproj, HH, DKS);
}

// ---------------------------------------------------------------------------
// Scores body (round-6 exact: f32 tanh.approx, raw logits; k3 masks).
// ---------------------------------------------------------------------------
__device__ __forceinline__ void scores_body(int bid, float (*ks)[512],
                                            const float* __restrict__ Wl)
{
    const int b  = bid >> 7;
    const int qg = (bid >> 2) & 31;
    const int mg = bid & 3;
    const int q0 = qg << 3;
    const int m0base = mg << 6;

    const int tid = threadIdx.x;
    const int lane = tid & 31;
    const int w = tid >> 5;
    const int q = q0 + w;

    float qr[16], wl[16];
    const float* qp = g_qproj + ((size_t)(b * QQ + q)) * HH;
#pragma unroll
    for (int j = 0; j < 16; j++) {
        qr[j] = qp[lane + 32 * j];
        wl[j] = Wl[lane + 32 * j];
    }

    float* lout = g_logits + ((size_t)(b * QQ + q)) * MMM;

    for (int t = 0; t < 4; t++) {
        const int m0 = m0base + (t << 4);
        __syncthreads();
        const float* kp = g_kproj + ((size_t)(b * MMM + m0)) * HH;
#pragma unroll
        for (int i = 0; i < 8; i++) {
            int idx = tid + (i << 8);
            int mm = idx >> 7;
            int c4 = (idx & 127) << 2;
            *reinterpret_cast<float4*>(&ks[mm][c4]) =
                *reinterpret_cast<const float4*>(kp + mm * HH + c4);
        }
        __syncthreads();

#pragma unroll 4
        for (int mm = 0; mm < 16; mm++) {
            float acc = 0.f;
#pragma unroll
            for (int j = 0; j < 16; j++) {
                float s = qr[j] + ks[mm][lane + 32 * j];
                float th;
                asm("tanh.approx.f32 %0, %1;" : "=f"(th) : "f"(s));
                acc = fmaf(wl[j], th, acc);
            }
#pragma unroll
            for (int o = 16; o > 0; o >>= 1)
                acc += __shfl_xor_sync(0xFFFFFFFFu, acc, o);
            if (lane == 0) lout[m0 + mm] = acc;
        }
    }
}

// ---------------------------------------------------------------------------
// K2: scores (512) + partial=query@Wo1^T+bo (128) + P2=memory@Wo2^T (128).
// (round-6 exact)
// ---------------------------------------------------------------------------
__global__ void __launch_bounds__(256) k2_scores_fused(
    const float* __restrict__ query, const float* __restrict__ memory,
    const float* __restrict__ Wo, const float* __restrict__ bo,
    const float* __restrict__ Wl)
{
    __shared__ __align__(16) union {
        float ks[16][512];                                 // 32 KB
        struct { float As[64][36]; float Ws[64][36]; } g;  // 18 KB
    } sm;

    const int bid = blockIdx.x;
    if (bid < 512) {
        scores_body(bid, sm.ks, Wl);
    } else if (bid < 640) {
        const int t = bid - 512;
        gemm_nt_256<true>(sm.g.As, sm.g.Ws, (t >> 3) << 6, (t & 7) << 6,
                          query, DQS, Wo, DC, bo, g_partial, DQS, DQS);
    } else {
        const int t = bid - 640;
        gemm_nt_256<false>(sm.g.As, sm.g.Ws, (t >> 3) << 6, (t & 7) << 6,
                           memory, DKS, Wo + DQS, DC, nullptr, g_P2, DQS, DKS);
    }
}

// ---------------------------------------------------------------------------
// K3: softmax + mask (round-6 exact). 256 blocks x 128 threads.
// ---------------------------------------------------------------------------
__global__ void __launch_bounds__(128) k3_softmax(
    const unsigned int* __restrict__ mask,
    float* __restrict__ weights)
{
    const int bid = blockIdx.x;
    const int b = bid >> 6;
    const int lane = threadIdx.x & 31;
    const int w = threadIdx.x >> 5;
    const int q = ((bid & 63) << 2) + w;

    const float* lin = g_logits + ((size_t)(b * QQ + q)) * MMM;
    const unsigned int* mrow = mask + b * MMM;

    float v[8];
    float mx = -3.4e38f;
#pragma unroll
    for (int j = 0; j < 8; j++) {
        int m = lane + 32 * j;
        float s = lin[m];
        if (mrow[m] != 0u) s = -1e18f;
        v[j] = s;
        mx = fmaxf(mx, s);
    }
#pragma unroll
    for (int o = 16; o > 0; o >>= 1)
        mx = fmaxf(mx, __shfl_xor_sync(0xFFFFFFFFu, mx, o));
    float sum = 0.f;
#pragma unroll
    for (int j = 0; j < 8; j++) {
        v[j] = __expf(v[j] - mx);
        sum += v[j];
    }
#pragma unroll
    for (int o = 16; o > 0; o >>= 1)
        sum += __shfl_xor_sync(0xFFFFFFFFu, sum, o);
    float inv = 1.f / sum;

    float* wout = weights + ((size_t)(b * QQ + q)) * MMM;
#pragma unroll
    for (int j = 0; j < 8; j++)
        wout[lane + 32 * j] = v[j] * inv;
}

// ---------------------------------------------------------------------------
// K4: out = tanh(partial + weights @ P2)  (batched NN, K = 256).
// ONE CHANGE vs round 6: 32x64 tiles, 128 thr, grid = 256 blocks
// (8 qt x 8 ct x 4 b) so all 148 SMs are covered with ~2 blocks/SM.
// Warp tile 32x16 (4 warps, 1x4). Double-buffered smem.
// ---------------------------------------------------------------------------
__global__ void __launch_bounds__(128) k4_final(
    const float* __restrict__ Wt, float* __restrict__ out)
{
    const int bid = blockIdx.x;
    const int b  = bid >> 6;
    const int qt = (bid >> 3) & 7;
    const int ct = bid & 7;
    const int row0 = qt << 5;   // 32-row q tile
    const int col0 = ct << 6;   // 64-col o tile

    const float* A  = Wt   + (size_t)b * QQ * MMM;   // weights, lda = MMM
    const float* Bm = g_P2 + (size_t)b * MMM * DQS;  // P2, ldb = DQS

    __shared__ float As[2][32][36];
    __shared__ float Bs[2][32][72];

    const int tid  = threadIdx.x;
    const int lane = tid & 31;
    const int g    = lane >> 2;
    const int tg   = lane & 3;
    const int w    = tid >> 5;
    const int wn   = w << 4;    // warp n-offset: 0,16,32,48

    // loaders: A 32x8 f4 = 256 (2/thread); B 32x16 f4 = 512 (4/thread)
    int ar[2], ac[2], br[4], bc[4];
#pragma unroll
    for (int c = 0; c < 2; c++) {
        int idx = tid + (c << 7);
        ar[c] = idx >> 3;  ac[c] = (idx & 7) << 2;
    }
#pragma unroll
    for (int c = 0; c < 4; c++) {
        int idx = tid + (c << 7);
        br[c] = idx >> 4;  bc[c] = (idx & 15) << 2;
    }

    float acc[2][2][4];
#pragma unroll
    for (int mi = 0; mi < 2; mi++)
#pragma unroll
        for (int ni = 0; ni < 2; ni++)
#pragma unroll
            for (int j = 0; j < 4; j++) acc[mi][ni][j] = 0.f;

    float4 pa[2], pb[4];
#pragma unroll
    for (int c = 0; c < 2; c++)
        pa[c] = *reinterpret_cast<const float4*>(A + (size_t)(row0 + ar[c]) * MMM + ac[c]);
#pragma unroll
    for (int c = 0; c < 4; c++)
        pb[c] = *reinterpret_cast<const float4*>(Bm + (size_t)br[c] * DQS + col0 + bc[c]);

    int buf = 0;
    for (int k0 = 0; k0 < MMM; k0 += 32) {
#pragma unroll
        for (int c = 0; c < 2; c++) {
            float4 va = pa[c];
            *reinterpret_cast<float4*>(&As[buf][ar[c]][ac[c]]) =
                make_float4(f2tf32(va.x), f2tf32(va.y), f2tf32(va.z), f2tf32(va.w));
        }
#pragma unroll
        for (int c = 0; c < 4; c++) {
            float4 vb = pb[c];
            *reinterpret_cast<float4*>(&Bs[buf][br[c]][bc[c]]) =
                make_float4(f2tf32(vb.x), f2tf32(vb.y), f2tf32(vb.z), f2tf32(vb.w));
        }
        __syncthreads();

        int kn = k0 + 32;
        if (kn < MMM) {
#pragma unroll
            for (int c = 0; c < 2; c++)
                pa[c] = *reinterpret_cast<const float4*>(
                    A + (size_t)(row0 + ar[c]) * MMM + kn + ac[c]);
#pragma unroll
            for (int c = 0; c < 4; c++)
                pb[c] = *reinterpret_cast<const float4*>(
                    Bm + (size_t)(kn + br[c]) * DQS + col0 + bc[c]);
        }

#pragma unroll
        for (int ks = 0; ks < 4; ks++) {
            const int kk = ks << 3;
            uint32_t af[2][4], bf[2][2];
#pragma unroll
            for (int mi = 0; mi < 2; mi++) {
                int r = (mi << 4) + g;
                af[mi][0] = fu(As[buf][r][kk + tg]);
                af[mi][1] = fu(As[buf][r + 8][kk + tg]);
                af[mi][2] = fu(As[buf][r][kk + tg + 4]);
                af[mi][3] = fu(As[buf][r + 8][kk + tg + 4]);
            }
#pragma unroll
            for (int ni = 0; ni < 2; ni++) {
                int cn = wn + (ni << 3) + g;
                bf[ni][0] = fu(Bs[buf][kk + tg][cn]);
                bf[ni][1] = fu(Bs[buf][kk + tg + 4][cn]);
            }
#pragma unroll
            for (int mi = 0; mi < 2; mi++)
#pragma unroll
                for (int ni = 0; ni < 2; ni++)
                    mma_tf32(acc[mi][ni], af[mi], bf[ni]);
        }
        buf ^= 1;
    }

#pragma unroll
    for (int mi = 0; mi < 2; mi++) {
#pragma unroll
        for (int ni = 0; ni < 2; ni++) {
            int col = col0 + wn + (ni << 3) + (tg << 1);
            size_t r0 = (size_t)b * QQ + row0 + (mi << 4) + g;
            size_t r1 = r0 + 8;
            float2 p0 = *reinterpret_cast<const float2*>(&g_partial[r0 * DQS + col]);
            float2 p1 = *reinterpret_cast<const float2*>(&g_partial[r1 * DQS + col]);
            *reinterpret_cast<float2*>(out + r0 * DQS + col) =
                make_float2(tanhf(acc[mi][ni][0] + p0.x), tanhf(acc[mi][ni][1] + p0.y));
            *reinterpret_cast<float2*>(out + r1 * DQS + col) =
                make_float2(tanhf(acc[mi][ni][2] + p1.x), tanhf(acc[mi][ni][3] + p1.y));
        }
    }
}

// ---------------------------------------------------------------------------
// Launch
// ---------------------------------------------------------------------------
extern "C" void kernel_launch(void* const* d_in, const int* in_sizes, int n_in,
                              void* d_out, int out_size)
{
    const float* query  = (const float*)d_in[0];
    const float* memory = (const float*)d_in[1];
    const unsigned int* mask = (const unsigned int*)d_in[2];
    const float* Wk = (const float*)d_in[3];
    const float* bk = (const float*)d_in[4];
    const float* Wq = (const float*)d_in[5];
    const float* bq = (const float*)d_in[6];
    const float* Wl = (const float*)d_in[7];
    // d_in[8] = bl (uniform shift — cancels in softmax)
    const float* Wo = (const float*)d_in[9];
    const float* bo = (const float*)d_in[10];

    float* out     = (float*)d_out;
    float* weights = out + BB * QQ * DQS;

    k1_proj<<<256, 256>>>(query, memory, Wq, bq, Wk, bk);
    k2_scores_fused<<<768, 256>>>(query, memory, Wo, bo, Wl);
    k3_softmax<<<256, 128>>>(mask, weights);
    k4_final<<<256, 128>>>(weights, out);
}